// round 13
// baseline (speedup 1.0000x reference)
#include <cuda_runtime.h>
#include <cuda_fp16.h>
#include <cstdint>

// ============================================================================
// GroupedMultiQueryAttention — full algebraic reduction, low-rank factored,
// SINGLE fused GEMM kernel.
//   out[g] = X[g] @ Wv[g] @ Weff[g]   (attention = 64*v; Weff folds Wo)
// Round 13: one CTA owns a 128-row strip.
//   Phase A: Y_strip(128x256) = fp16(X_strip) @ WvT^T  — two 128-col
//     sub-passes (acc reuse), X via register-convert path, 2-stage rings;
//     epilogue writes Y into resident SMEM (no DRAM round-trip).
//   Phase B: out_strip(128x1024) = Y_strip @ WeffT^T — 8 n-blocks x 4 k-iters
//     streaming WeffT through a 2-stage ring aliased over phase-A rings;
//     A-fragments ldmatrix'd from resident Y.
// Grid 256 CTAs = one full wave at 2 CTAs/SM.
// ============================================================================

#define NG    8
#define NEMB  1024
#define KVDIM 256
#define MROWS 4096
#define NRAT  4
#define NHD   64

// ---------------- static device scratch -------------------------------------
__device__ __half g_wt  [NG * NEMB * KVDIM];   // WeffT fp16 [g][o=1024][c=256]
__device__ __half g_wvt [NG * KVDIM * NEMB];   // WvT  fp16 [g][c=256][i=1024]

// ---------------- PTX helpers ------------------------------------------------
__device__ __forceinline__ uint32_t smem_u32(const void* p) {
    uint32_t a;
    asm("{ .reg .u64 t; cvta.to.shared.u64 t, %1; cvt.u32.u64 %0, t; }" : "=r"(a) : "l"(p));
    return a;
}
__device__ __forceinline__ void cp16(uint32_t dst, const void* src) {
    asm volatile("cp.async.cg.shared.global [%0], [%1], 16;" :: "r"(dst), "l"(src));
}
#define CP_COMMIT() asm volatile("cp.async.commit_group;" ::: "memory")
#define CP_WAIT(n)  asm volatile("cp.async.wait_group %0;" :: "n"(n) : "memory")

__device__ __forceinline__ void ldsm_x4(uint32_t* r, uint32_t addr) {
    asm volatile("ldmatrix.sync.aligned.m8n8.x4.shared.b16 {%0,%1,%2,%3}, [%4];"
                 : "=r"(r[0]), "=r"(r[1]), "=r"(r[2]), "=r"(r[3]) : "r"(addr));
}
__device__ __forceinline__ void mma_fp16(float* d, const uint32_t* a, const uint32_t* b) {
    asm volatile("mma.sync.aligned.m16n8k16.row.col.f32.f16.f16.f32 "
                 "{%0,%1,%2,%3}, {%4,%5,%6,%7}, {%8,%9}, {%0,%1,%2,%3};"
                 : "+f"(d[0]), "+f"(d[1]), "+f"(d[2]), "+f"(d[3])
                 : "r"(a[0]), "r"(a[1]), "r"(a[2]), "r"(a[3]), "r"(b[0]), "r"(b[1]));
}
__device__ __forceinline__ void ldg128(float* v, const float* p) {
    asm volatile("ld.global.v4.f32 {%0,%1,%2,%3}, [%4];"
                 : "=f"(v[0]), "=f"(v[1]), "=f"(v[2]), "=f"(v[3]) : "l"(p));
}

// ---------------- smem layout --------------------------------------------------
#define BLDA 264                              // Y row stride (halfs): 33x16B, odd -> conflict-free ldsm
#define Y_BYTES (128 * BLDA * 2)              // 67584
// phase A rings (aliased by phase B W-ring)
#define XBK  32
#define XLDT 40
#define XSTAGE (128 * XLDT * 2)               // 10240
#define RING_BASE Y_BYTES
#define XA_RING RING_BASE                     // 2 x 10240
#define XB_RING (RING_BASE + 2 * XSTAGE)      // 2 x 10240
// phase B WeffT ring (aliases [RING_BASE, RING_BASE+36864))
#define BLDB 72
#define WSTAGE (128 * BLDB * 2)               // 18432
#define W_RING RING_BASE
#define SMEM_TOT (Y_BYTES + 4 * XSTAGE)       // 108544

// ============================================================================
__global__ void __launch_bounds__(256, 2)
fused_gemm_kernel(const float* __restrict__ X, const __half* __restrict__ WvT,
                  const __half* __restrict__ WeffT, float* __restrict__ out) {
    extern __shared__ char smem[];
    const uint32_t sbase = smem_u32(smem);
    const int tid = threadIdx.x, wid = tid >> 5, lid = tid & 31;
    const int g = blockIdx.y;
    const int mBase = blockIdx.x * 128;

    const float*  x0 = X + (size_t)g * MROWS * NEMB + (size_t)mBase * NEMB;
    float* c0 = out + (size_t)g * MROWS * NEMB + (size_t)mBase * NEMB;

    const int wm = (wid >> 2) * 64, wn = (wid & 3) * 32;
    const int lr = lid & 7, ls = lid >> 3;
    const uint32_t aRow = (uint32_t)((ls & 1) * 8 + lr);
    const uint32_t aK   = (uint32_t)((ls >> 1) * 8);
    const uint32_t bRow = (uint32_t)(((lid >> 4) & 1) * 8 + lr);
    const uint32_t bK   = (uint32_t)(((lid >> 3) & 1) * 8);
    const int er = lid >> 2, ec = (lid & 3) * 2;

    // X LDG mapping: 4 groups/thread; coalesced 4 rows x 128B per instr
    const float* aptr[4];
    uint32_t stsOff[4];
#pragma unroll
    for (int j = 0; j < 4; j++) {
        int idx = tid + j * 256, row = idx >> 3, c4 = idx & 7;
        aptr[j] = x0 + (size_t)row * NEMB + c4 * 4;
        stsOff[j] = (uint32_t)(row * XLDT + c4 * 4) * 2;
    }

    float acc[4][4][4];

    // ========================= PHASE A: Y = fp16(X) @ WvT^T ==================
#pragma unroll 1
    for (int h = 0; h < 2; h++) {
        const __half* b0 = WvT + (size_t)g * KVDIM * NEMB + (size_t)h * 128 * NEMB;

#pragma unroll
        for (int mt = 0; mt < 4; mt++)
#pragma unroll
            for (int nt = 0; nt < 4; nt++)
#pragma unroll
                for (int q = 0; q < 4; q++) acc[mt][nt][q] = 0.f;

        auto cpB = [&](int s, int k0) {
#pragma unroll
            for (int i = 0; i < 2; i++) {
                int op = tid + i * 256, row = op >> 2, cc = op & 3;
                cp16(sbase + XB_RING + (uint32_t)s * XSTAGE
                         + (uint32_t)(row * XLDT + cc * 8) * 2,
                     b0 + (size_t)row * NEMB + k0 + cc * 8);
            }
        };
        float rA[16];
        auto ldgA = [&](int k0) {
#pragma unroll
            for (int j = 0; j < 4; j++) ldg128(rA + j * 4, aptr[j] + k0);
        };
        auto stsA = [&](int s) {
            const uint32_t st = sbase + XA_RING + (uint32_t)s * XSTAGE;
#pragma unroll
            for (int j = 0; j < 4; j++) {
                __half2 p0 = __floats2half2_rn(rA[j*4+0], rA[j*4+1]);
                __half2 p1 = __floats2half2_rn(rA[j*4+2], rA[j*4+3]);
                asm volatile("st.shared.v2.b32 [%0], {%1,%2};"
                             :: "r"(st + stsOff[j]),
                                "r"(*(uint32_t*)&p0), "r"(*(uint32_t*)&p1));
            }
        };

        const int nk = NEMB / XBK;             // 32
        // prologue
        ldgA(0); stsA(0); cpB(0, 0); CP_COMMIT();
        ldgA(XBK);

        for (int it = 0; it < nk; ++it) {
            CP_WAIT(0);
            __syncthreads();
            if (it + 1 < nk) { stsA((it + 1) & 1); cpB((it + 1) & 1, (it + 1) * XBK); }
            if (it + 2 < nk) ldgA((it + 2) * XBK);
            CP_COMMIT();

            const uint32_t ast = sbase + XA_RING + (uint32_t)(it & 1) * XSTAGE;
            const uint32_t bst = sbase + XB_RING + (uint32_t)(it & 1) * XSTAGE;
#pragma unroll
            for (int kk = 0; kk < XBK; kk += 16) {
                uint32_t bf[4][2];
#pragma unroll
                for (int p = 0; p < 2; p++) {
                    uint32_t r[4];
                    uint32_t ro = (uint32_t)((wn + p * 16 + bRow) * XLDT + kk + bK) * 2;
                    ldsm_x4(r, bst + ro);
                    bf[p * 2 + 0][0] = r[0]; bf[p * 2 + 0][1] = r[1];
                    bf[p * 2 + 1][0] = r[2]; bf[p * 2 + 1][1] = r[3];
                }
#pragma unroll
                for (int mt = 0; mt < 4; mt++) {
                    uint32_t a[4];
                    uint32_t ro = (uint32_t)((wm + mt * 16 + aRow) * XLDT + kk + aK) * 2;
                    ldsm_x4(a, ast + ro);
#pragma unroll
                    for (int nt = 0; nt < 4; nt++)
                        mma_fp16(acc[mt][nt], a, bf[nt]);
                }
            }
        }
        CP_WAIT(0);
        __syncthreads();                        // rings free; Y region private

        // epilogue: acc -> resident Y smem (cols h*128 + ...)
#pragma unroll
        for (int mt = 0; mt < 4; mt++)
#pragma unroll
            for (int nt = 0; nt < 4; nt++) {
                int row = wm + mt * 16 + er;
                int col = h * 128 + wn + nt * 8 + ec;
                __half2 v01 = __floats2half2_rn(acc[mt][nt][0], acc[mt][nt][1]);
                __half2 v23 = __floats2half2_rn(acc[mt][nt][2], acc[mt][nt][3]);
                *(uint32_t*)(smem + (size_t)row * BLDA * 2 + col * 2) = *(uint32_t*)&v01;
                *(uint32_t*)(smem + (size_t)(row + 8) * BLDA * 2 + col * 2) = *(uint32_t*)&v23;
            }
        __syncthreads();
    }

    // ========================= PHASE B: out = Y @ WeffT^T ====================
    const __half* wb = WeffT + (size_t)g * NEMB * KVDIM;

    auto loadW = [&](int s, int t) {           // t in [0,32): j=t>>2 (n-block), k=(t&3)*64
        const __half* src = wb + (size_t)(t >> 2) * 128 * KVDIM + (t & 3) * 64;
        const uint32_t dst = sbase + W_RING + (uint32_t)s * WSTAGE;
#pragma unroll
        for (int i = 0; i < 4; i++) {
            int op = tid + i * 256, row = op >> 3, cc = op & 7;
            cp16(dst + (uint32_t)(row * BLDB + cc * 8) * 2,
                 src + (size_t)row * KVDIM + cc * 8);
        }
    };

    loadW(0, 0); CP_COMMIT();

#pragma unroll
    for (int mt = 0; mt < 4; mt++)
#pragma unroll
        for (int nt = 0; nt < 4; nt++)
#pragma unroll
            for (int q = 0; q < 4; q++) acc[mt][nt][q] = 0.f;

#pragma unroll 1
    for (int t = 0; t < 32; ++t) {
        CP_WAIT(0);
        __syncthreads();
        if (t + 1 < 32) loadW((t + 1) & 1, t + 1);
        CP_COMMIT();

        const uint32_t bst = sbase + W_RING + (uint32_t)(t & 1) * WSTAGE;
        const int kg = (t & 3) * 64;           // K offset within resident Y
#pragma unroll
        for (int kk = 0; kk < 64; kk += 16) {
            uint32_t bf[4][2];
#pragma unroll
            for (int p = 0; p < 2; p++) {
                uint32_t r[4];
                uint32_t ro = (uint32_t)((wn + p * 16 + bRow) * BLDB + kk + bK) * 2;
                ldsm_x4(r, bst + ro);
                bf[p * 2 + 0][0] = r[0]; bf[p * 2 + 0][1] = r[1];
                bf[p * 2 + 1][0] = r[2]; bf[p * 2 + 1][1] = r[3];
            }
#pragma unroll
            for (int mt = 0; mt < 4; mt++) {
                uint32_t a[4];
                uint32_t ro = (uint32_t)((wm + mt * 16 + aRow) * BLDA + kg + kk + aK) * 2;
                ldsm_x4(a, sbase + ro);
#pragma unroll
                for (int nt = 0; nt < 4; nt++)
                    mma_fp16(acc[mt][nt], a, bf[nt]);
            }
        }

        if ((t & 3) == 3) {                    // n-block done: store + reset acc
            const int nb = t >> 2;
#pragma unroll
            for (int mt = 0; mt < 4; mt++)
#pragma unroll
                for (int nt = 0; nt < 4; nt++) {
                    int row = wm + mt * 16 + er;
                    int col = nb * 128 + wn + nt * 8 + ec;
                    *(float2*)&c0[(size_t)row * NEMB + col] =
                        make_float2(acc[mt][nt][0], acc[mt][nt][1]);
                    *(float2*)&c0[(size_t)(row + 8) * NEMB + col] =
                        make_float2(acc[mt][nt][2], acc[mt][nt][3]);
#pragma unroll
                    for (int q = 0; q < 4; q++) acc[mt][nt][q] = 0.f;
                }
        }
    }
}

// ---------------- helper kernels --------------------------------------------
// fused fold + transpose + fp16:
// WeffT[g][o][c] = fp16( 64 * sum_r Wo[g][(kv*4+r)*64+d][o] ),  c = kv*64+d
__global__ void fold_transpose_kernel(const float* __restrict__ Wo,
                                      __half* __restrict__ out) {
    __shared__ float t[32][33];
    const int g = blockIdx.z;
    const int oB = blockIdx.x * 32;
    const int cB = blockIdx.y * 32;
    const int tx = threadIdx.x, ty = threadIdx.y;   // 32 x 8
    const float* wo = Wo + (size_t)g * NEMB * NEMB;
#pragma unroll
    for (int j = 0; j < 4; j++) {
        int cc = cB + ty + j * 8;
        int kv = cc >> 6, d = cc & 63;
        int o = oB + tx;
        float s = 0.f;
#pragma unroll
        for (int r = 0; r < NRAT; r++)
            s += wo[(size_t)((kv * NRAT + r) * NHD + d) * NEMB + o];
        t[ty + j * 8][tx] = 64.0f * s;
    }
    __syncthreads();
    __half* O = out + (size_t)g * NEMB * KVDIM;
#pragma unroll
    for (int j = 0; j < 4; j++) {
        float x = t[tx][ty + j * 8];
        O[(size_t)(oB + ty + j * 8) * KVDIM + cB + tx] = __float2half_rn(x);
    }
}

__global__ void transpose_half_kernel(const float* __restrict__ in,
                                      __half* __restrict__ out, int R, int Cc) {
    __shared__ float t[32][33];
    const int g = blockIdx.z;
    const int cB = blockIdx.x * 32, rB = blockIdx.y * 32;
    const int tx = threadIdx.x, ty = threadIdx.y;
#pragma unroll
    for (int j = 0; j < 4; j++)
        t[ty + j * 8][tx] = in[(size_t)g * R * Cc + (size_t)(rB + ty + j * 8) * Cc + cB + tx];
    __syncthreads();
    __half* O = out + (size_t)g * R * Cc;
#pragma unroll
    for (int j = 0; j < 4; j++) {
        float x = t[tx][ty + j * 8];
        O[(size_t)(cB + ty + j * 8) * R + rB + tx] = __float2half_rn(x);
    }
}

// ---------------- launch -----------------------------------------------------
extern "C" void kernel_launch(void* const* d_in, const int* in_sizes, int n_in,
                              void* d_out, int out_size) {
    const float* tensor = (const float*)d_in[0];
    const float* Wv = (const float*)d_in[3];
    const float* Wo = (const float*)d_in[4];
    float* out = (float*)d_out;

    cudaFuncSetAttribute(fused_gemm_kernel,
                         cudaFuncAttributeMaxDynamicSharedMemorySize, SMEM_TOT);

    __half *wt, *wvt;
    cudaGetSymbolAddress((void**)&wt,  g_wt);
    cudaGetSymbolAddress((void**)&wvt, g_wvt);

    // 1. fold+transpose: Wo -> WeffT fp16 [g][1024][256]
    {
        dim3 grid(NEMB / 32, KVDIM / 32, NG);
        fold_transpose_kernel<<<grid, dim3(32, 8)>>>(Wo, wt);
    }
    // 2. Wv [1024][256] -> WvT fp16 [256][1024]
    {
        dim3 grid(KVDIM / 32, NEMB / 32, NG);
        transpose_half_kernel<<<grid, dim3(32, 8)>>>(Wv, wvt, NEMB, KVDIM);
    }
    // 3. fused: out = (fp16(X) @ WvT^T) @ WeffT^T   — 256 CTAs, one wave
    {
        dim3 grid(MROWS / 128, NG);            // (32, 8)
        fused_gemm_kernel<<<grid, 256, SMEM_TOT>>>(tensor, wvt, wt, out);
    }
}